// round 1
// baseline (speedup 1.0000x reference)
#include <cuda_runtime.h>
#include <stdint.h>

// Problem shape (fixed by the dataset): B=512, T=4096, L=15.
#define B_ 512
#define T_ 4096
#define L_ 15
#define LOG2E 1.4426950408889634f
#define LN2   0.6931471805599453f
#define PF 8   // emission prefetch depth (per-step serial latency ~80cyc * 8 > DRAM 577cyc)

// Scratch (device globals: no allocation allowed in kernel_launch)
__device__ float g_num[B_];
__device__ float g_den[B_];
__device__ int   g_seqlen[B_];

// ---------------------------------------------------------------------------
// dtype sniffing: labels may be int32 or int64 (jax x64 ambiguity), mask may
// be uint8 (numpy bool) or int32. Values are in [0,15) and mask[:,0]=1, so:
//  - int64 labels: every odd 32-bit word is 0 (prob ~ (1/15)^32 of false hit).
//  - int32 mask:   bytes 1..3 of each word are 0 while byte 0 is 1.
// ---------------------------------------------------------------------------
__device__ __forceinline__ bool detect_labels64(const void* labels) {
    const unsigned* w = (const unsigned*)labels;
    bool all0 = true;
#pragma unroll
    for (int i = 0; i < 32; i++) all0 &= (w[2 * i + 1] == 0u);
    return all0;
}
__device__ __forceinline__ bool detect_mask32(const void* mask) {
    const uint8_t* mb = (const uint8_t*)mask;
    bool i32 = (mb[0] != 0);
#pragma unroll
    for (int k = 0; k < 4; k++)
        i32 &= (mb[4 * k + 1] == 0 && mb[4 * k + 2] == 0 && mb[4 * k + 3] == 0);
    return i32;
}
__device__ __forceinline__ int get_label(const void* p, bool is64, long idx) {
    return is64 ? (int)(((const long long*)p)[idx]) : ((const int*)p)[idx];
}
__device__ __forceinline__ bool get_mask(const void* p, bool is32, long idx) {
    return is32 ? (((const int*)p)[idx] != 0) : (((const uint8_t*)p)[idx] != 0);
}

// ---------------------------------------------------------------------------
// Kernel 1: gold-path numerator + sequence length. One block per batch.
// ---------------------------------------------------------------------------
__global__ void __launch_bounds__(128) crf_num_kernel(
    const float* __restrict__ em, const float* __restrict__ trans,
    const float* __restrict__ start, const float* __restrict__ endt,
    const void* __restrict__ labels, const void* __restrict__ mask)
{
    __shared__ float s_trans[L_ * L_];
    __shared__ float s_acc[128];
    __shared__ int   s_cnt[128];
    __shared__ int   s_flags;

    const int b = blockIdx.x;
    const int tid = threadIdx.x;

    if (tid == 0)
        s_flags = (detect_labels64(labels) ? 1 : 0) | (detect_mask32(mask) ? 2 : 0);
    for (int i = tid; i < L_ * L_; i += 128) s_trans[i] = trans[i];
    __syncthreads();
    const bool is64 = (s_flags & 1) != 0;
    const bool m32  = (s_flags & 2) != 0;

    const long base = (long)b * T_;
    float acc = 0.f;
    int cnt = 0;
    for (int t = tid; t < T_; t += 128) {
        bool m = get_mask(mask, m32, base + t);
        if (m) {
            int lt = get_label(labels, is64, base + t);
            acc += em[(base + t) * (long)L_ + lt];
            cnt++;
            if (t > 0) {
                int lp = get_label(labels, is64, base + t - 1);
                acc += s_trans[lp * L_ + lt];
            }
        }
    }
    s_acc[tid] = acc;
    s_cnt[tid] = cnt;
    __syncthreads();
    for (int s = 64; s > 0; s >>= 1) {
        if (tid < s) { s_acc[tid] += s_acc[tid + s]; s_cnt[tid] += s_cnt[tid + s]; }
        __syncthreads();
    }
    if (tid == 0) {
        int seqlen = s_cnt[0];
        int l0 = get_label(labels, is64, base);
        int llast = get_label(labels, is64, base + seqlen - 1);
        g_num[b] = start[l0] + s_acc[0] + endt[llast];
        g_seqlen[b] = seqlen;
    }
}

// ---------------------------------------------------------------------------
// Kernel 2: log-partition via bidirectional probability-domain forward scan.
// One warp per batch: lanes 0-15 run the forward (alpha) recurrence, lanes
// 16-31 run the backward (beta) recurrence; they meet in the middle.
//   alpha_t = (alpha_{t-1} . Etrans) * exp(em_t)        (lane j owns col j)
//   beta_{t-1} = Etrans . (exp(em_t) * beta_t)          (lane i owns row i)
//   Z = sum_j alpha_m[j] * beta_m[j]
// Exact power-of-2 renormalization every PF steps keeps fp32 in range.
// ---------------------------------------------------------------------------
__global__ void __launch_bounds__(128) crf_den_kernel(
    const float* __restrict__ em, const float* __restrict__ trans,
    const float* __restrict__ start, const float* __restrict__ endt)
{
    const int warp = threadIdx.x >> 5;
    const int lane = threadIdx.x & 31;
    const int b = blockIdx.x * 4 + warp;
    const int half = lane >> 4;      // 0 = forward, 1 = backward
    const int j = lane & 15;
    const bool active = (j < L_);

    // Per-lane transition coefficients: forward lane j needs column j,
    // backward lane i needs row i. exp(-10000) underflows to exactly 0,
    // matching the reference's logsumexp behavior for forbidden transitions.
    float tc[L_];
#pragma unroll
    for (int k = 0; k < L_; k++) {
        float tv = active ? (half ? trans[j * L_ + k] : trans[k * L_ + j]) : -1e30f;
        tc[k] = exp2f(tv * LOG2E);
    }

    const float* base = em + (long)b * T_ * L_;
    const int Tp = g_seqlen[b];
    const int nf = Tp >> 1;          // forward steps (t = 1..nf) -> alpha_nf
    const int nb = Tp - 1 - nf;      // backward steps (t = Tp-1..nf+1) -> beta_nf
    const int common = nb;           // nb <= nf always
    const int extra = nf - nb;       // 0 or 1 (forward-only tail step)

    float state;
    const float* ptr;
    int stride;
    if (half == 0) {
        state = active ? exp2f((start[j] + base[j]) * LOG2E) : 0.f;
        ptr = base + L_ + j;
        stride = L_;
    } else {
        state = active ? exp2f(endt[j] * LOG2E) : 0.f;
        ptr = base + (long)(Tp - 1) * L_ + j;
        stride = -L_;
    }
    if (!active) { ptr = base; stride = 0; }   // keep inactive lanes in-bounds

    int Cacc = 0;  // log2 scale accumulated by renormalization

    // One recurrence step. e = exp(em) for this lane's (t, j).
    // Forward scales AFTER the matvec; backward scales BEFORE the broadcast.
    auto step = [&](float e, bool commit_upper) {
        float re = state * e;
        float r = half ? re : state;
        float a[5] = {0.f, 0.f, 0.f, 0.f, 0.f};
#pragma unroll
        for (int k = 0; k < L_; k++) {
            float rk = __shfl_sync(0xffffffffu, r, k, 16);
            a[k % 5] = fmaf(tc[k], rk, a[k % 5]);
        }
        float accv = ((a[0] + a[1]) + (a[2] + a[3])) + a[4];
        float ns = half ? accv : accv * e;
        bool commit = (half == 0) || commit_upper;
        state = commit ? ns : state;
    };

    // Exact scaling by 2^-ex where ex = exponent of lane 0's state (components
    // stay within a few powers of e of each other, so one pivot suffices).
    auto renorm = [&]() {
        float s = __shfl_sync(0xffffffffu, state, 0, 16);
        int ex = ((__float_as_int(s) >> 23) & 0xff) - 127;
        ex = max(-126, min(126, ex));
        state *= __int_as_float((127 - ex) << 23);
        Cacc += ex;
    };

    if (Tp >= 2 * PF + 2) {
        // Software-pipelined path: PF-deep emission prefetch.
        float q[PF];
#pragma unroll
        for (int u = 0; u < PF; u++) { q[u] = __ldg(ptr); ptr += stride; }

        const int main_iters = common & ~(PF - 1);
        for (int i = 0; i < main_iters; i += PF) {
#pragma unroll
            for (int u = 0; u < PF; u++) {
                float e = exp2f(q[u] * LOG2E);
                q[u] = __ldg(ptr); ptr += stride;   // prefetch step i+PF+u
                step(e, true);
            }
            renorm();
        }
        const int rem = common - main_iters;   // < PF, warp-uniform
        float qextra = 0.f;
#pragma unroll
        for (int u = 0; u < PF; u++) {
            if (u == rem) qextra = q[u];
            if (u < rem) { step(exp2f(q[u] * LOG2E), true); }
        }
        if (extra) step(exp2f(qextra * LOG2E), false);
    } else {
        // Tiny-sequence fallback (not hit for this dataset).
        for (int s = 0; s < common; s++) {
            float v = __ldg(ptr); ptr += stride;
            step(exp2f(v * LOG2E), true);
        }
        if (extra) {
            float v = __ldg(ptr);
            step(exp2f(v * LOG2E), false);
        }
    }
    renorm();

    // Combine: lane j pairs with lane j+16 -> alpha_m[j]*beta_m[j], reduce.
    float other = __shfl_xor_sync(0xffffffffu, state, 16);
    float prod = state * other;
    prod += __shfl_xor_sync(0xffffffffu, prod, 8, 16);
    prod += __shfl_xor_sync(0xffffffffu, prod, 4, 16);
    prod += __shfl_xor_sync(0xffffffffu, prod, 2, 16);
    prod += __shfl_xor_sync(0xffffffffu, prod, 1, 16);
    int Cother = __shfl_xor_sync(0xffffffffu, Cacc, 16);
    if (lane == 0)
        g_den[b] = logf(prod) + (float)(Cacc + Cother) * LN2;
}

// ---------------------------------------------------------------------------
// Kernel 3: loss = mean(denominator - numerator), double accumulation.
// ---------------------------------------------------------------------------
__global__ void __launch_bounds__(B_) crf_reduce_kernel(float* __restrict__ out)
{
    __shared__ double sd[B_];
    int t = threadIdx.x;
    sd[t] = (double)g_den[t] - (double)g_num[t];
    __syncthreads();
    for (int s = B_ / 2; s > 0; s >>= 1) {
        if (t < s) sd[t] += sd[t + s];
        __syncthreads();
    }
    if (t == 0) out[0] = (float)(sd[0] / (double)B_);
}

// ---------------------------------------------------------------------------
extern "C" void kernel_launch(void* const* d_in, const int* in_sizes, int n_in,
                              void* d_out, int out_size)
{
    const float* em    = (const float*)d_in[0];   // emissions [512,4096,15] f32
    const float* trans = (const float*)d_in[1];   // transitions [15,15]
    const float* start = (const float*)d_in[2];   // start_transitions [15]
    const float* endt  = (const float*)d_in[3];   // end_transitions [15]
    const void*  labels = d_in[4];                // labels [512,4096] i32/i64
    const void*  mask   = d_in[5];                // mask [512,4096] u8/i32
    (void)in_sizes; (void)n_in; (void)out_size;

    crf_num_kernel<<<B_, 128>>>(em, trans, start, endt, labels, mask);
    crf_den_kernel<<<B_ / 4, 128>>>(em, trans, start, endt);
    crf_reduce_kernel<<<1, B_>>>((float*)d_out);
}

// round 2
// speedup vs baseline: 1.1429x; 1.1429x over previous
#include <cuda_runtime.h>
#include <stdint.h>

// Problem shape (fixed by dataset): B=512, T=4096, L=15.
#define B_ 512
#define T_ 4096
#define L_ 15
#define LOG2E 1.4426950408889634f
#define LN2   0.6931471805599453f
#define PF 8          // emission prefetch depth
#define DEN_BLOCKS 128   // 4 batches/block, 1 warp per batch (fwd+bwd halves)
#define NUM_BLOCKS 512   // 1 batch/block

__device__ float g_num[B_];
__device__ float g_den[B_];

// ---------------- packed f32x2 helpers (sm_103a) ----------------
typedef unsigned long long u64t;
__device__ __forceinline__ u64t pk2(float lo, float hi) {
    u64t r; asm("mov.b64 %0,{%1,%2};" : "=l"(r) : "f"(lo), "f"(hi)); return r;
}
__device__ __forceinline__ u64t mul2(u64t a, u64t b) {
    u64t d; asm("mul.rn.f32x2 %0,%1,%2;" : "=l"(d) : "l"(a), "l"(b)); return d;
}
__device__ __forceinline__ u64t fma2(u64t a, u64t b, u64t c) {
    u64t d; asm("fma.rn.f32x2 %0,%1,%2,%3;" : "=l"(d) : "l"(a), "l"(b), "l"(c)); return d;
}
__device__ __forceinline__ u64t add2(u64t a, u64t b) {
    u64t d; asm("add.rn.f32x2 %0,%1,%2;" : "=l"(d) : "l"(a), "l"(b)); return d;
}
__device__ __forceinline__ void unpk2(u64t a, float& l, float& h) {
    asm("mov.b64 {%0,%1},%2;" : "=f"(l), "=f"(h) : "l"(a));
}

// ---------------- dtype sniffing ----------------
__device__ __forceinline__ bool detect_labels64(const void* labels) {
    const unsigned* w = (const unsigned*)labels;
    bool all0 = true;
#pragma unroll
    for (int i = 0; i < 32; i++) all0 &= (w[2 * i + 1] == 0u);
    return all0;
}
__device__ __forceinline__ bool detect_mask32(const void* mask) {
    const uint8_t* mb = (const uint8_t*)mask;
    bool i32 = (mb[0] != 0);
#pragma unroll
    for (int k = 0; k < 4; k++)
        i32 &= (mb[4 * k + 1] == 0 && mb[4 * k + 2] == 0 && mb[4 * k + 3] == 0);
    return i32;
}
__device__ __forceinline__ int get_label(const void* p, bool is64, long idx) {
    return is64 ? (int)(((const long long*)p)[idx]) : ((const int*)p)[idx];
}
__device__ __forceinline__ bool get_mask(const void* p, bool is32, long idx) {
    return is32 ? (((const int*)p)[idx] != 0) : (((const uint8_t*)p)[idx] != 0);
}

// ---------------------------------------------------------------------------
// Merged kernel: blocks [0, DEN_BLOCKS) run the log-partition recurrence
// (latency-bound, issue-starved); blocks [DEN_BLOCKS, DEN_BLOCKS+NUM_BLOCKS)
// run the gold-path numerator (memory-bound) concurrently, filling the idle
// pipes.
// ---------------------------------------------------------------------------
__global__ void __launch_bounds__(128) crf_main_kernel(
    const float* __restrict__ em, const float* __restrict__ trans,
    const float* __restrict__ start, const float* __restrict__ endt,
    const void* __restrict__ labels, const void* __restrict__ mask)
{
    // den: [warp][phase][lane] double-buffered broadcast staging
    __shared__ __align__(16) float sbuf[4][2][32];
    // num: scratch
    __shared__ float s_trans[L_ * L_];
    __shared__ float s_acc[128];
    __shared__ int   s_cnt[128];
    __shared__ int   s_flags;

    if (blockIdx.x < DEN_BLOCKS) {
        // =================== DENOMINATOR (forward algorithm) ===================
        // One warp per batch. Lanes 0-15: forward alpha recurrence (lane j owns
        // state j). Lanes 16-31: backward beta recurrence. Meet in the middle:
        // Z = sum_j alpha_m[j] * beta_m[j]. Probability domain with exact
        // power-of-2 renormalization; exp(-10000) forbidden transitions -> 0.
        const int warp = threadIdx.x >> 5;
        const int lane = threadIdx.x & 31;
        const int b = blockIdx.x * 4 + warp;
        const int half = lane >> 4;
        const int j = lane & 15;
        const bool active = (j < L_);

        // --- sequence length from mask (prefix-contiguous per torchcrf) ---
        const bool m32 = detect_mask32(mask);
        const long mbase = (long)b * T_;
        int cnt = 0;
        if (m32) {
            const uint4* mp = (const uint4*)((const int*)mask + mbase);
#pragma unroll
            for (int i = lane; i < T_ / 4; i += 32) {
                uint4 v = mp[i];
                cnt += (v.x != 0) + (v.y != 0) + (v.z != 0) + (v.w != 0);
            }
        } else {
            const uint4* mp = (const uint4*)((const uint8_t*)mask + mbase);
#pragma unroll
            for (int i = lane; i < T_ / 16; i += 32) {
                uint4 v = mp[i];
                unsigned s = v.x + v.y + v.z + v.w;  // bool bytes: no carries
                cnt += (int)((s & 0xff) + ((s >> 8) & 0xff) +
                             ((s >> 16) & 0xff) + ((s >> 24) & 0xff));
            }
        }
#pragma unroll
        for (int s = 16; s; s >>= 1) cnt += __shfl_xor_sync(0xffffffffu, cnt, s);
        const int Tp = cnt;

        // --- per-lane transition coefficients, packed in f32x2 pairs ---
        // fwd lane j: column j of trans; bwd lane i: row i. Pad slot 15 -> 0.
        u64t tc2[8];
        {
            float tcv[16];
#pragma unroll
            for (int k = 0; k < 16; k++) {
                float tv = -1e30f;
                if (active && k < L_) tv = half ? trans[j * L_ + k] : trans[k * L_ + j];
                tcv[k] = exp2f(tv * LOG2E);
            }
#pragma unroll
            for (int k2 = 0; k2 < 8; k2++) tc2[k2] = pk2(tcv[2 * k2], tcv[2 * k2 + 1]);
        }

        const float* base = em + (long)b * T_ * L_;
        const int nf = Tp >> 1;
        const int nb = Tp - 1 - nf;
        const int common = nb;
        const int extra = nf - nb;   // 0 or 1 forward-only tail step

        float state;
        const float* ptr;
        int stride;
        if (half == 0) {
            state = active ? exp2f((start[j] + base[j]) * LOG2E) : 0.f;
            ptr = base + L_ + j;  stride = L_;
        } else {
            state = active ? exp2f(endt[j] * LOG2E) : 0.f;
            ptr = base + (long)(Tp - 1) * L_ + j;  stride = -L_;
        }
        if (!active) { ptr = base; stride = 0; }

        float* wb = sbuf[warp][0];   // phase stride = 32 floats
        int phase = 0;
        int Cacc = 0;
        float lastr0 = 1.0f;         // renorm pivot, refreshed each step for free

        // One recurrence step. e = exp(em) for this lane's (t, j).
        auto step = [&](float e, bool commit_upper) {
            float re = state * e;
            float r = half ? re : state;
            wb[phase * 32 + lane] = r;          // STS: 32 consecutive floats, no conflicts
            __syncwarp();
            const ulonglong2* rb =
                (const ulonglong2*)(wb + phase * 32 + half * 16);
            ulonglong2 w0 = rb[0], w1 = rb[1], w2 = rb[2], w3 = rb[3];  // 4x LDS.128 broadcast
            u64t a0 = mul2(tc2[0], w0.x); a0 = fma2(tc2[4], w2.x, a0);
            u64t a1 = mul2(tc2[1], w0.y); a1 = fma2(tc2[5], w2.y, a1);
            u64t a2 = mul2(tc2[2], w1.x); a2 = fma2(tc2[6], w3.x, a2);
            u64t a3 = mul2(tc2[3], w1.y); a3 = fma2(tc2[7], w3.y, a3);
            u64t s01 = add2(a0, a1), s23 = add2(a2, a3), sm = add2(s01, s23);
            float l, h; unpk2(sm, l, h);
            float accv = l + h;
            { float p0, p1; unpk2(w0.x, p0, p1); lastr0 = p0; }
            float ns = half ? accv : accv * e;
            state = (half == 0 || commit_upper) ? ns : state;
            phase ^= 1;
        };

        auto renorm = [&]() {
            int ex = ((__float_as_int(lastr0) >> 23) & 0xff) - 127;
            ex = max(-126, min(126, ex));
            state *= __int_as_float((127 - ex) << 23);
            Cacc += ex;
        };

        if (Tp >= 2 * PF + 2) {
            float q[PF];
#pragma unroll
            for (int u = 0; u < PF; u++) { q[u] = __ldg(ptr); ptr += stride; }
            const int main_iters = common & ~(PF - 1);
            for (int i = 0; i < main_iters; i += PF) {
                float ee[PF];
#pragma unroll
                for (int u = 0; u < PF; u++) ee[u] = exp2f(q[u] * LOG2E);
#pragma unroll
                for (int u = 0; u < PF; u++) {
                    q[u] = __ldg(ptr); ptr += stride;   // refill PF ahead
                    step(ee[u], true);
                }
                renorm();
            }
            const int rem = common - main_iters;   // warp-uniform, < PF
            float qextra = 0.f;
#pragma unroll
            for (int u = 0; u < PF; u++) {
                if (u == rem) qextra = q[u];
                if (u < rem) step(exp2f(q[u] * LOG2E), true);
            }
            if (extra) step(exp2f(qextra * LOG2E), false);
        } else {
            for (int s = 0; s < common; s++) {
                float v = __ldg(ptr); ptr += stride;
                step(exp2f(v * LOG2E), true);
            }
            if (extra) { float v = __ldg(ptr); step(exp2f(v * LOG2E), false); }
        }
        renorm();   // bound magnitudes before the fp32 product below

        // Combine: lane j pairs with lane j+16 -> alpha_m[j]*beta_m[j]; reduce.
        float other = __shfl_xor_sync(0xffffffffu, state, 16);
        float prod = state * other;
        prod += __shfl_xor_sync(0xffffffffu, prod, 8, 16);
        prod += __shfl_xor_sync(0xffffffffu, prod, 4, 16);
        prod += __shfl_xor_sync(0xffffffffu, prod, 2, 16);
        prod += __shfl_xor_sync(0xffffffffu, prod, 1, 16);
        int Cother = __shfl_xor_sync(0xffffffffu, Cacc, 16);
        if (lane == 0)
            g_den[b] = logf(prod) + (float)(Cacc + Cother) * LN2;

    } else {
        // =================== NUMERATOR (gold path score) ===================
        const int b = blockIdx.x - DEN_BLOCKS;
        const int tid = threadIdx.x;

        if (tid == 0)
            s_flags = (detect_labels64(labels) ? 1 : 0) | (detect_mask32(mask) ? 2 : 0);
        for (int i = tid; i < L_ * L_; i += 128) s_trans[i] = trans[i];
        __syncthreads();
        const bool is64 = (s_flags & 1) != 0;
        const bool m32  = (s_flags & 2) != 0;

        const long base = (long)b * T_;
        float acc = 0.f;
        int cnt = 0;
        for (int t = tid; t < T_; t += 128) {
            bool m = get_mask(mask, m32, base + t);
            if (m) {
                int lt = get_label(labels, is64, base + t);
                acc += em[(base + t) * (long)L_ + lt];
                cnt++;
                if (t > 0) {
                    int lp = get_label(labels, is64, base + t - 1);
                    acc += s_trans[lp * L_ + lt];
                }
            }
        }
        s_acc[tid] = acc;
        s_cnt[tid] = cnt;
        __syncthreads();
        for (int s = 64; s > 0; s >>= 1) {
            if (tid < s) { s_acc[tid] += s_acc[tid + s]; s_cnt[tid] += s_cnt[tid + s]; }
            __syncthreads();
        }
        if (tid == 0) {
            int seqlen = s_cnt[0];
            int l0 = get_label(labels, is64, base);
            int llast = get_label(labels, is64, base + seqlen - 1);
            g_num[b] = start[l0] + s_acc[0] + endt[llast];
        }
    }
}

// ---------------------------------------------------------------------------
// loss = mean(denominator - numerator), double accumulation.
// ---------------------------------------------------------------------------
__global__ void __launch_bounds__(B_) crf_reduce_kernel(float* __restrict__ out)
{
    __shared__ double sd[B_];
    int t = threadIdx.x;
    sd[t] = (double)g_den[t] - (double)g_num[t];
    __syncthreads();
    for (int s = B_ / 2; s > 0; s >>= 1) {
        if (t < s) sd[t] += sd[t + s];
        __syncthreads();
    }
    if (t == 0) out[0] = (float)(sd[0] / (double)B_);
}

// ---------------------------------------------------------------------------
extern "C" void kernel_launch(void* const* d_in, const int* in_sizes, int n_in,
                              void* d_out, int out_size)
{
    const float* em    = (const float*)d_in[0];   // emissions [512,4096,15] f32
    const float* trans = (const float*)d_in[1];   // transitions [15,15]
    const float* start = (const float*)d_in[2];   // start_transitions [15]
    const float* endt  = (const float*)d_in[3];   // end_transitions [15]
    const void*  labels = d_in[4];                // labels [512,4096] i32/i64
    const void*  mask   = d_in[5];                // mask [512,4096] u8/i32
    (void)in_sizes; (void)n_in; (void)out_size;

    crf_main_kernel<<<DEN_BLOCKS + NUM_BLOCKS, 128>>>(em, trans, start, endt, labels, mask);
    crf_reduce_kernel<<<1, B_>>>((float*)d_out);
}